// round 13
// baseline (speedup 1.0000x reference)
#include <cuda_runtime.h>
#include <cuda_bf16.h>
#include <cstdint>

// Problem constants (fixed by the reference setup_inputs)
#define B_   256
#define N_   4096
#define D_   64            // KD == VD == 64
#define RD_  65            // KD + 1
#define CHUNKS_ (N_ / 128) // rows per block = 128 -> 32 chunks

// ---------------- scratch (no allocations allowed) ----------------
__device__ float g_sim[B_ * N_];     // similarity, masked slots = 0
__device__ float g_m[B_];            // softmax row max
__device__ float g_is[B_];           // 1 / sum(exp(sim - m))
__device__ float g_acc[B_ * D_];     // partial read accumulator (cols 0..63)
__device__ int   g_it64;             // 1 if iteration buffer is int64, 0 if int32

// iteration dtype sniffing: values are in [0, 4096). If the buffer is int64
// (little-endian), the int32 view has zero high words at every odd index.
// If it is int32, odd indices are random iterations — P(all 128 zero) ~ 0.
__global__ void k_detect(const int* __restrict__ it32)
{
    int acc = 0;
#pragma unroll 8
    for (int i = 1; i < 2 * B_ - 1; i += 2) acc |= it32[i];
    g_it64 = (acc == 0) ? 1 : 0;
}

__device__ __forceinline__ long long load_it(const void* p, int b)
{
    return g_it64 ? ((const long long*)p)[b]
                  : (long long)((const int*)p)[b];
}

// ============================================================================
// Kernel 1: copy value_memory -> out_vm rows [0,N) AND compute sim[b][n].
// Block = 256 threads: 16 threads per row (4 floats each), 16 rows per pass,
// 8 passes -> 128 rows per block. Grid = (32, B).
// ============================================================================
__global__ __launch_bounds__(256) void k_vm_sim(
    const float* __restrict__ vm, const float* __restrict__ nv,
    const void* __restrict__ iteration, float* __restrict__ out_vm)
{
    const int b    = blockIdx.y;
    const int lane = threadIdx.x & 15;   // column group: 4 floats
    const int rgrp = threadIdx.x >> 4;   // 0..15 row within pass
    const long long it = load_it(iteration, b);

    const float4 nv4 = *reinterpret_cast<const float4*>(nv + b * D_ + lane * 4);
    const float* vmb = vm     + (size_t)b * N_ * D_;
    float*       ovb = out_vm + (size_t)b * (N_ + 1) * D_;
    const int n0 = blockIdx.x * 128;

#pragma unroll
    for (int p = 0; p < 8; ++p) {
        const int n = n0 + p * 16 + rgrp;
        const float4 v = *reinterpret_cast<const float4*>(vmb + (size_t)n * D_ + lane * 4);
        *reinterpret_cast<float4*>(ovb + (size_t)n * D_ + lane * 4) = v;
        float part = v.x * nv4.x + v.y * nv4.y + v.z * nv4.z + v.w * nv4.w;
#pragma unroll
        for (int off = 8; off; off >>= 1)
            part += __shfl_down_sync(0xffffffffu, part, off, 16);
        if (lane == 0)
            g_sim[(size_t)b * N_ + n] = (n <= it) ? part : 0.0f;  // masked -> sim exactly 0
    }
}

// ============================================================================
// Kernel 2: per-batch softmax stats (m, 1/S), confidence reduction -> read[64],
// and zero g_acc. One block per batch, 256 threads, sim row in smem (16 KB).
// ============================================================================
__global__ __launch_bounds__(256) void k_softmax(
    const float* __restrict__ w_conf, const float* __restrict__ b_conf,
    const float* __restrict__ gate, const void* __restrict__ iteration,
    float* __restrict__ out_read)
{
    const int b   = blockIdx.x;
    const int tid = threadIdx.x;
    __shared__ float ssim[N_];
    __shared__ float sred[256];

    const float* simb = g_sim + (size_t)b * N_;
    float mx = -1e30f;
    for (int i = tid; i < N_; i += 256) { float v = simb[i]; ssim[i] = v; mx = fmaxf(mx, v); }
    sred[tid] = mx; __syncthreads();
    for (int s = 128; s; s >>= 1) { if (tid < s) sred[tid] = fmaxf(sred[tid], sred[tid + s]); __syncthreads(); }
    const float m = sred[0]; __syncthreads();

    float sum = 0.0f;
    for (int i = tid; i < N_; i += 256) sum += __expf(ssim[i] - m);
    sred[tid] = sum; __syncthreads();
    for (int s = 128; s; s >>= 1) { if (tid < s) sred[tid] += sred[tid + s]; __syncthreads(); }
    const float inv = 1.0f / sred[0]; __syncthreads();

    // confidence column: sum_n wv[n] * sigmoid(sim[n]*w + bconf)
    const float w  = w_conf[0];
    const float bc = b_conf[0];
    float cs = 0.0f;
    for (int i = tid; i < N_; i += 256) {
        const float s_ = ssim[i];
        const float wv = __expf(s_ - m) * inv;
        const float conf = 1.0f / (1.0f + __expf(-(s_ * w + bc)));
        cs += wv * conf;
    }
    sred[tid] = cs; __syncthreads();
    for (int s = 128; s; s >>= 1) { if (tid < s) sred[tid] += sred[tid + s]; __syncthreads(); }

    if (tid == 0) {
        g_m[b]  = m;
        g_is[b] = inv;
        const bool nf = load_it(iteration, b) > 1;
        const float sg = 1.0f / (1.0f + __expf(-gate[b * RD_ + D_]));
        out_read[b * RD_ + D_] = nf ? sg * sred[0] : 0.0f;
    }
    if (tid < D_) g_acc[b * D_ + tid] = 0.0f;
}

// ============================================================================
// Kernel 3: copy key_memory -> out_km rows [0,N) AND accumulate
// read[0..63] += wv[n] * km[n][:]. Same tiling as kernel 1. Grid = (32, B).
// ============================================================================
__global__ __launch_bounds__(256) void k_km_read(
    const float* __restrict__ km, float* __restrict__ out_km)
{
    const int b    = blockIdx.y;
    const int lane = threadIdx.x & 15;
    const int rgrp = threadIdx.x >> 4;
    __shared__ float sh[16 * D_];

    const float m   = g_m[b];
    const float inv = g_is[b];
    const float* kmb  = km     + (size_t)b * N_ * D_;
    float*       okb  = out_km + (size_t)b * (N_ + 1) * D_;
    const float* simb = g_sim  + (size_t)b * N_;
    const int n0 = blockIdx.x * 128;

    float4 acc = make_float4(0.f, 0.f, 0.f, 0.f);
#pragma unroll
    for (int p = 0; p < 8; ++p) {
        const int n = n0 + p * 16 + rgrp;
        const float4 v = *reinterpret_cast<const float4*>(kmb + (size_t)n * D_ + lane * 4);
        *reinterpret_cast<float4*>(okb + (size_t)n * D_ + lane * 4) = v;
        float wv = 0.0f;
        if (lane == 0) wv = __expf(simb[n] - m) * inv;
        wv = __shfl_sync(0xffffffffu, wv, 0, 16);  // broadcast within 16-lane row group
        acc.x += wv * v.x; acc.y += wv * v.y; acc.z += wv * v.z; acc.w += wv * v.w;
    }

    *reinterpret_cast<float4*>(sh + rgrp * D_ + lane * 4) = acc;
    __syncthreads();
    if (threadIdx.x < D_) {
        float s = 0.0f;
#pragma unroll
        for (int g = 0; g < 16; ++g) s += sh[g * D_ + threadIdx.x];
        atomicAdd(&g_acc[b * D_ + threadIdx.x], s);
    }
}

// ============================================================================
// Kernel 4: gate+mask the read vector (cols 0..63) and append new_key /
// new_value at slot n = N. Grid = B, 128 threads.
// ============================================================================
__global__ __launch_bounds__(128) void k_final(
    const float* __restrict__ gate, const void* __restrict__ iteration,
    const float* __restrict__ new_key, const float* __restrict__ new_value,
    float* __restrict__ out_km, float* __restrict__ out_vm,
    float* __restrict__ out_read)
{
    const int b = blockIdx.x;
    const int t = threadIdx.x;
    if (t < D_) {
        const bool nf = load_it(iteration, b) > 1;
        const float sg = 1.0f / (1.0f + __expf(-gate[b * RD_ + t]));
        out_read[b * RD_ + t] = nf ? sg * g_acc[b * D_ + t] : 0.0f;
        out_km[(size_t)b * (N_ + 1) * D_ + (size_t)N_ * D_ + t] = new_key[b * D_ + t];
    } else {
        const int d = t - D_;
        out_vm[(size_t)b * (N_ + 1) * D_ + (size_t)N_ * D_ + d] = new_value[b * D_ + d];
    }
}

// ============================================================================
extern "C" void kernel_launch(void* const* d_in, const int* in_sizes, int n_in,
                              void* d_out, int out_size)
{
    const float* new_key   = (const float*)d_in[0];      // [B, 64]
    const float* new_value = (const float*)d_in[1];      // [B, 64]
    const float* km        = (const float*)d_in[2];      // [B, N, 64]
    const float* vm        = (const float*)d_in[3];      // [B, N, 64]
    const float* gate      = (const float*)d_in[4];      // [B, 65]
    const float* w_conf    = (const float*)d_in[5];      // [1, 1]
    const float* b_conf    = (const float*)d_in[6];      // [1]
    const void*  iteration = d_in[7];                    // [B, 1] int32 or int64

    float* out = (float*)d_out;
    float* out_km   = out;                                     // [B, N+1, 64]
    float* out_vm   = out_km + (size_t)B_ * (N_ + 1) * D_;     // [B, N+1, 64]
    float* out_read = out_vm + (size_t)B_ * (N_ + 1) * D_;     // [B, 65]

    dim3 gridCopy(CHUNKS_, B_);
    k_detect  <<<1, 1>>>((const int*)iteration);
    k_vm_sim  <<<gridCopy, 256>>>(vm, new_value, iteration, out_vm);
    k_softmax <<<B_, 256>>>(w_conf, b_conf, gate, iteration, out_read);
    k_km_read <<<gridCopy, 256>>>(km, out_km);
    k_final   <<<B_, 128>>>(gate, iteration, new_key, new_value,
                            out_km, out_vm, out_read);
}